// round 15
// baseline (speedup 1.0000x reference)
#include <cuda_runtime.h>
#include <cuda_bf16.h>
#include <cstdint>
#include <cstddef>

// 256 graphs x 64 nodes; E=1048576 rows (r = b*4096 + i*64 + j); C=64.
// K1: X=SP@W4^T/64, Y=SP@W5^T/64 -> hi/lo bf16 PLANES [b*64+c][4096]
//     (TWO column-half passes w/ acc reuse -> 3 CTAs/SM)
// K2: per (b, channel-pair): prod_c = X_c @ Y_c (REVERSE bid order)
// K3: out = relu(SP@W6a^T + prod@W6b^T)
// mma.sync m16n8k16 bf16; 3-term split via register reuse of hi/lo planes.
// Staging via cp.async. All GEMM kernels at 3 CTAs/SM.

__device__ unsigned short g_Xh[67108864];
__device__ unsigned short g_Xl[67108864];
__device__ unsigned short g_Yh[67108864];
__device__ unsigned short g_Yl[67108864];
__device__ unsigned short g_ph[67108864];
__device__ unsigned short g_pl[67108864];
__device__ unsigned short g_Wk1[128 * 136];
__device__ unsigned short g_Wk3[64 * 280];

#define AK2  136
#define K2BS 72
#define BK3  280

__device__ __forceinline__ uint32_t smem_u32(const void* p) {
    uint32_t a; asm("{ .reg .u64 t; cvta.to.shared.u64 t, %1; cvt.u32.u64 %0, t; }" : "=r"(a) : "l"(p));
    return a;
}
__device__ __forceinline__ void cpa16(uint32_t sdst, const void* gsrc) {
    asm volatile("cp.async.cg.shared.global [%0], [%1], 16;" :: "r"(sdst), "l"(gsrc) : "memory");
}
#define CPA_WAIT() do { asm volatile("cp.async.commit_group;" ::: "memory"); \
                        asm volatile("cp.async.wait_group 0;" ::: "memory"); } while (0)
__device__ __forceinline__ void splitb(float v, unsigned short& h, unsigned short& l) {
    __nv_bfloat16 hb = __float2bfloat16_rn(v);
    float r = v - __bfloat162float(hb);
    __nv_bfloat16 lb = __float2bfloat16_rn(r);
    h = reinterpret_cast<unsigned short&>(hb);
    l = reinterpret_cast<unsigned short&>(lb);
}
__device__ __forceinline__ uint32_t splitpack(float v) {
    unsigned short h, l; splitb(v, h, l);
    return (uint32_t)h | ((uint32_t)l << 16);
}
__device__ __forceinline__ uint32_t prmt(uint32_t a, uint32_t b, uint32_t s) {
    uint32_t d; asm("prmt.b32 %0,%1,%2,%3;" : "=r"(d) : "r"(a), "r"(b), "r"(s)); return d;
}
__device__ __forceinline__ void ldsm4(uint32_t* r, uint32_t a) {
    asm volatile("ldmatrix.sync.aligned.m8n8.x4.shared.b16 {%0,%1,%2,%3}, [%4];"
                 : "=r"(r[0]), "=r"(r[1]), "=r"(r[2]), "=r"(r[3]) : "r"(a));
}
__device__ __forceinline__ void ldsm4t(uint32_t* r, uint32_t a) {
    asm volatile("ldmatrix.sync.aligned.m8n8.x4.trans.shared.b16 {%0,%1,%2,%3}, [%4];"
                 : "=r"(r[0]), "=r"(r[1]), "=r"(r[2]), "=r"(r[3]) : "r"(a));
}
__device__ __forceinline__ void mma16(float* c, const uint32_t* a, uint32_t b0, uint32_t b1) {
    asm volatile("mma.sync.aligned.m16n8k16.row.col.f32.bf16.bf16.f32 "
                 "{%0,%1,%2,%3},{%4,%5,%6,%7},{%8,%9},{%0,%1,%2,%3};"
                 : "+f"(c[0]), "+f"(c[1]), "+f"(c[2]), "+f"(c[3])
                 : "r"(a[0]), "r"(a[1]), "r"(a[2]), "r"(a[3]), "r"(b0), "r"(b1));
}

// ===================== weight prep =====================
__global__ void wprep(const float* __restrict__ W4, const float* __restrict__ W5,
                      const float* __restrict__ W6) {
    const int tid = threadIdx.x;
#pragma unroll
    for (int it = 0; it < 8; it++) {
        int idx = tid + it * 256;
        int n = idx >> 4, k0 = (idx & 15) * 4;
        float4 v = (n < 64) ? ((const float4*)W4)[idx] : ((const float4*)W5)[idx - 1024];
        unsigned short h0,l0,h1,l1,h2,l2,h3,l3;
        splitb(v.x,h0,l0); splitb(v.y,h1,l1); splitb(v.z,h2,l2); splitb(v.w,h3,l3);
        *(uint2*)&g_Wk1[n*AK2 + k0]      = make_uint2((uint32_t)h0|((uint32_t)h1<<16), (uint32_t)h2|((uint32_t)h3<<16));
        *(uint2*)&g_Wk1[n*AK2 + 64 + k0] = make_uint2((uint32_t)l0|((uint32_t)l1<<16), (uint32_t)l2|((uint32_t)l3<<16));
    }
#pragma unroll
    for (int it = 0; it < 8; it++) {
        int idx = tid + it * 256;
        int o = idx >> 5, m0 = (idx & 31) * 4;
        float4 v = ((const float4*)W6)[idx];
        unsigned short h0,l0,h1,l1,h2,l2,h3,l3;
        splitb(v.x,h0,l0); splitb(v.y,h1,l1); splitb(v.z,h2,l2); splitb(v.w,h3,l3);
        int s = (m0 < 64) ? 0 : 136;
        int k0 = m0 & 63;
        *(uint2*)&g_Wk3[o*BK3 + s + k0]      = make_uint2((uint32_t)h0|((uint32_t)h1<<16), (uint32_t)h2|((uint32_t)h3<<16));
        *(uint2*)&g_Wk3[o*BK3 + s + 64 + k0] = make_uint2((uint32_t)l0|((uint32_t)l1<<16), (uint32_t)l2|((uint32_t)l3<<16));
    }
}

// ===================== K1: two column-half passes, 3 CTAs/SM =====================
__global__ __launch_bounds__(256, 3) void k1(const float* __restrict__ SP) {
    extern __shared__ char smraw[];
    unsigned short* As = (unsigned short*)smraw;               // [128][AK2]
    unsigned short* Bs = (unsigned short*)(smraw + 34816);     // [128][AK2]
    uint32_t* Ds = (uint32_t*)(smraw + 34816);                 // overlays Bs rows 0-63 (dead after pass-1 MMA)
    const int tid = threadIdx.x;
    const int row0 = blockIdx.x * 128;
    const int b = row0 >> 12, rig = row0 & 4095;
    const uint32_t as_u = smem_u32(As), bs_u = smem_u32(Bs);

    for (int idx = tid; idx < 2176; idx += 256)
        cpa16(bs_u + idx * 16, (const char*)g_Wk1 + idx * 16);

    const float4* SPg = (const float4*)(SP + (size_t)row0 * 64);
#pragma unroll
    for (int it = 0; it < 8; it++) {
        int idx = tid + it * 256;
        float4 v = SPg[idx];
        int r = idx >> 4, k0 = (idx & 15) * 4;
        unsigned short h0,l0,h1,l1,h2,l2,h3,l3;
        splitb(v.x,h0,l0); splitb(v.y,h1,l1); splitb(v.z,h2,l2); splitb(v.w,h3,l3);
        *(uint2*)&As[r*AK2 + k0]      = make_uint2((uint32_t)h0|((uint32_t)h1<<16), (uint32_t)h2|((uint32_t)h3<<16));
        *(uint2*)&As[r*AK2 + 64 + k0] = make_uint2((uint32_t)l0|((uint32_t)l1<<16), (uint32_t)l2|((uint32_t)l3<<16));
    }
    CPA_WAIT();
    __syncthreads();

    const int warp = tid >> 5, lane = tid & 31;
    const int lrow = lane & 15, lcol8 = (lane >> 4) * 8;
    const int mh = warp >> 2;                         // m-half owned by this warp
    const int mr = mh * 64, nc = (warp & 3) * 16;
    const int g = lane >> 2, t2 = (lane & 3) * 2;

    // NOTE on pass-1 Bs overlay: pass-1 MMA reads Bs rows 0-63; after the
    // post-MMA sync those rows are dead and Ds ([64c][68] u32 = 17408B) fits there.
    for (int p = 0; p < 2; p++) {
        float acc[4][2][4] = {};
#pragma unroll
        for (int kt = 0; kt < 4; kt++) {
            const int kk = kt * 16;
            uint32_t ah[4][4], al[4][4], bh[4], bl[4];
#pragma unroll
            for (int mt = 0; mt < 4; mt++) {
                uint32_t basea = as_u + (uint32_t)(((mr + mt*16 + lrow) * AK2) + kk + lcol8) * 2;
                ldsm4(ah[mt], basea);
                ldsm4(al[mt], basea + 128);
            }
            {
                uint32_t baseb = bs_u + (uint32_t)(((p*64 + nc + lrow) * AK2) + kk + lcol8) * 2;
                ldsm4(bh, baseb);
                ldsm4(bl, baseb + 128);
            }
            // [n][k] x4: {b0@nc, b0@nc+8, b1@nc, b1@nc+8}
#pragma unroll
            for (int mt = 0; mt < 4; mt++) {
                mma16(acc[mt][0], ah[mt], bh[0], bh[2]);
                mma16(acc[mt][0], ah[mt], bl[0], bl[2]);
                mma16(acc[mt][0], al[mt], bh[0], bh[2]);
                mma16(acc[mt][1], ah[mt], bh[1], bh[3]);
                mma16(acc[mt][1], ah[mt], bl[1], bl[3]);
                mma16(acc[mt][1], al[mt], bh[1], bh[3]);
            }
        }
        __syncthreads();

        // epilogue: per m-half so Ds ([64c][68]) fits the dead Bs window
        for (int hh = 0; hh < 2; hh++) {
            if (mh == hh) {
#pragma unroll
                for (int mt = 0; mt < 4; mt++)
#pragma unroll
                    for (int nt = 0; nt < 2; nt++) {
                        int ml = mt*16 + g;
                        int col = nc + nt*8 + t2;
                        Ds[col*68 + ml]         = splitpack(acc[mt][nt][0] * 0.015625f);
                        Ds[(col+1)*68 + ml]     = splitpack(acc[mt][nt][1] * 0.015625f);
                        Ds[col*68 + ml + 8]     = splitpack(acc[mt][nt][2] * 0.015625f);
                        Ds[(col+1)*68 + ml + 8] = splitpack(acc[mt][nt][3] * 0.015625f);
                    }
            }
            __syncthreads();
#pragma unroll
            for (int it = 0; it < 4; it++) {
                int idx = tid + it * 256;             // 1024 uint4 = 64c x 16
                int c = idx >> 4, m4 = (idx & 15) * 4;
                uint4 v = *(const uint4*)&Ds[c*68 + m4];
                uint2 hi = make_uint2(prmt(v.x, v.y, 0x5410), prmt(v.z, v.w, 0x5410));
                uint2 lo = make_uint2(prmt(v.x, v.y, 0x7632), prmt(v.z, v.w, 0x7632));
                size_t off = (size_t)(b*64 + c)*4096 + rig + hh*64 + m4;
                if (p == 0) { *(uint2*)&g_Xh[off] = hi; *(uint2*)&g_Xl[off] = lo; }
                else        { *(uint2*)&g_Yh[off] = hi; *(uint2*)&g_Yl[off] = lo; }
            }
            __syncthreads();
        }
    }
}

// ===================== K2 (reverse bid order for L2 reuse) =====================
__global__ __launch_bounds__(256, 3) void k2() {
    extern __shared__ char smraw[];
    unsigned short* As = (unsigned short*)smraw;      // [128][AK2]  [X_c1; X_c2]
    unsigned short* Bs = As + 128 * AK2;              // 2 x [128][K2BS]
    const int tid = threadIdx.x;
    const int bidr = 8191 - blockIdx.x;
    const int b = bidr >> 5, c1 = (bidr & 31) * 2;
    const size_t base = (size_t)(b*64 + c1) * 4096;
    const uint32_t as_u = smem_u32(As);
    const uint32_t bs_u0 = smem_u32(Bs);

#pragma unroll
    for (int it = 0; it < 8; it++) {
        int idx = tid + it * 256;
        int m = idx >> 4, pl = (idx >> 3) & 1, c8 = (idx & 7) * 8;
        const unsigned short* src = (pl ? g_Xl : g_Xh) + base + (size_t)m * 64 + c8;
        cpa16(as_u + (uint32_t)(m*AK2 + pl*64 + c8) * 2, src);
    }
#pragma unroll
    for (int it = 0; it < 8; it++) {
        int idx = tid + it * 256;
        int cid = idx >> 10, r = (idx >> 3) & 127, j8 = (idx & 7) * 8;
        const unsigned short* src = ((r < 64) ? g_Yh : g_Yl) + base + (size_t)cid * 4096
                                    + (size_t)(r & 63) * 64 + j8;
        cpa16(bs_u0 + (uint32_t)(cid*128*K2BS + r*K2BS + j8) * 2, src);
    }
    CPA_WAIT();
    __syncthreads();

    const int warp = tid >> 5, lane = tid & 31;
    const int lrow = lane & 15, lcol8 = (lane >> 4) * 8;
    const int hf = warp >> 2;
    const int mr = hf * 64, n0 = (warp & 3) * 16;
    const uint32_t bs_u = bs_u0 + (uint32_t)(hf * 128 * K2BS) * 2;
    const int brow = (lane & 7) + 8 * ((lane >> 3) & 1);
    const int bcol = n0 + 8 * (lane >> 4);
    float acc[4][2][4] = {};

#pragma unroll
    for (int kt = 0; kt < 4; kt++) {
        const int kk = kt * 16;
        uint32_t ah[4][4], al[4][4], bh[4], bl[4];
#pragma unroll
        for (int mt = 0; mt < 4; mt++) {
            uint32_t basea = as_u + (uint32_t)(((mr + mt*16 + lrow) * AK2) + kk + lcol8) * 2;
            ldsm4(ah[mt], basea);
            ldsm4(al[mt], basea + 128);
        }
        ldsm4t(bh, bs_u + (uint32_t)(((kk + brow) * K2BS) + bcol) * 2);
        ldsm4t(bl, bs_u + (uint32_t)(((64 + kk + brow) * K2BS) + bcol) * 2);
#pragma unroll
        for (int mt = 0; mt < 4; mt++) {
            mma16(acc[mt][0], ah[mt], bh[0], bh[1]);
            mma16(acc[mt][0], ah[mt], bl[0], bl[1]);
            mma16(acc[mt][0], al[mt], bh[0], bh[1]);
            mma16(acc[mt][1], ah[mt], bh[2], bh[3]);
            mma16(acc[mt][1], ah[mt], bl[2], bl[3]);
            mma16(acc[mt][1], al[mt], bh[2], bh[3]);
        }
    }
    __syncthreads();

    uint32_t* Ds = (uint32_t*)smraw;                  // [128][68] packed
    const int g = lane >> 2, t2 = (lane & 3) * 2;
#pragma unroll
    for (int mt = 0; mt < 4; mt++)
#pragma unroll
        for (int nt = 0; nt < 2; nt++) {
            int row = mr + mt*16 + g;
            int jl = (warp & 3) * 16 + nt*8 + t2;
            Ds[row*68 + jl]         = splitpack(acc[mt][nt][0]);
            Ds[row*68 + jl + 1]     = splitpack(acc[mt][nt][1]);
            Ds[(row+8)*68 + jl]     = splitpack(acc[mt][nt][2]);
            Ds[(row+8)*68 + jl + 1] = splitpack(acc[mt][nt][3]);
        }
    __syncthreads();
#pragma unroll
    for (int it = 0; it < 8; it++) {
        int idx = tid + it * 256;
        int row = idx >> 4, j4 = (idx & 15) * 4;
        uint4 v = *(const uint4*)&Ds[row*68 + j4];
        uint2 hi = make_uint2(prmt(v.x, v.y, 0x5410), prmt(v.z, v.w, 0x5410));
        uint2 lo = make_uint2(prmt(v.x, v.y, 0x7632), prmt(v.z, v.w, 0x7632));
        size_t off = base + (size_t)row * 64 + j4;
        *(uint2*)&g_ph[off] = hi; *(uint2*)&g_pl[off] = lo;
    }
}

// ===================== K3 =====================
__global__ __launch_bounds__(256, 3) void k3(const float* __restrict__ SP,
                                             float* __restrict__ out) {
    extern __shared__ char smraw[];
    unsigned short* As = (unsigned short*)smraw;               // [128][AK2]
    unsigned short* Bs = (unsigned short*)(smraw + 128*AK2*2); // [64][BK3]
    const int tid = threadIdx.x;
    const int row0 = blockIdx.x * 128;
    const int b = row0 >> 12, rig = row0 & 4095;
    const uint32_t as_u = smem_u32(As);
    const uint32_t bs_u = smem_u32(Bs);

    for (int idx = tid; idx < 2240; idx += 256)
        cpa16(bs_u + idx * 16, (const char*)g_Wk3 + idx * 16);

    const float4* SPg = (const float4*)(SP + (size_t)row0 * 64);
#pragma unroll
    for (int it = 0; it < 8; it++) {
        int idx = tid + it * 256;
        float4 v = SPg[idx];
        int r = idx >> 4, k0 = (idx & 15) * 4;
        unsigned short h0,l0,h1,l1,h2,l2,h3,l3;
        splitb(v.x,h0,l0); splitb(v.y,h1,l1); splitb(v.z,h2,l2); splitb(v.w,h3,l3);
        *(uint2*)&As[r*AK2 + k0]      = make_uint2((uint32_t)h0|((uint32_t)h1<<16), (uint32_t)h2|((uint32_t)h3<<16));
        *(uint2*)&As[r*AK2 + 64 + k0] = make_uint2((uint32_t)l0|((uint32_t)l1<<16), (uint32_t)l2|((uint32_t)l3<<16));
    }
    CPA_WAIT();
    __syncthreads();

    const int warp = tid >> 5, lane = tid & 31;
    const int lrow = lane & 15, lcol8 = (lane >> 4) * 8;
    const int mr = (warp >> 2) * 64, nc = (warp & 3) * 16;
    float acc[4][2][4] = {};

#pragma unroll
    for (int kt = 0; kt < 4; kt++) {                  // pass 1: SP @ W6a^T
        const int kk = kt * 16;
        uint32_t ah[4][4], al[4][4], bh[4], bl[4];
#pragma unroll
        for (int mt = 0; mt < 4; mt++) {
            uint32_t basea = as_u + (uint32_t)(((mr + mt*16 + lrow) * AK2) + kk + lcol8) * 2;
            ldsm4(ah[mt], basea);
            ldsm4(al[mt], basea + 128);
        }
        {
            uint32_t baseb = bs_u + (uint32_t)(((nc + lrow) * BK3) + kk + lcol8) * 2;
            ldsm4(bh, baseb);
            ldsm4(bl, baseb + 128);
        }
#pragma unroll
        for (int mt = 0; mt < 4; mt++) {
            mma16(acc[mt][0], ah[mt], bh[0], bh[2]);
            mma16(acc[mt][0], ah[mt], bl[0], bl[2]);
            mma16(acc[mt][0], al[mt], bh[0], bh[2]);
            mma16(acc[mt][1], ah[mt], bh[1], bh[3]);
            mma16(acc[mt][1], ah[mt], bl[1], bl[3]);
            mma16(acc[mt][1], al[mt], bh[1], bh[3]);
        }
    }
    __syncthreads();

    // restage A = prod in [k=c][m] layout via cp.async
#pragma unroll
    for (int it = 0; it < 8; it++) {
        int idx = tid + it * 256;
        int r = idx >> 4, m8 = (idx & 15) * 8;
        int c = r & 63;
        const unsigned short* src = ((r < 64) ? g_ph : g_pl)
                                    + (size_t)(b*64 + c) * 4096 + rig + m8;
        cpa16(as_u + (uint32_t)(r*AK2 + m8) * 2, src);
    }
    CPA_WAIT();
    __syncthreads();

    const int arow = (lane & 7) + 8 * (lane >> 4);
    const int acol8 = 8 * ((lane >> 3) & 1);
#pragma unroll
    for (int kt = 0; kt < 4; kt++) {                  // pass 2: + prod @ W6b^T
        const int kk = kt * 16;
        uint32_t ah[4][4], al[4][4], bh[4], bl[4];
#pragma unroll
        for (int mt = 0; mt < 4; mt++) {
            ldsm4t(ah[mt], as_u + (uint32_t)(((kk + arow) * AK2) + mr + mt*16 + acol8) * 2);
            ldsm4t(al[mt], as_u + (uint32_t)(((64 + kk + arow) * AK2) + mr + mt*16 + acol8) * 2);
        }
        {
            uint32_t baseb = bs_u + (uint32_t)(((nc + lrow) * BK3) + 136 + kk + lcol8) * 2;
            ldsm4(bh, baseb);
            ldsm4(bl, baseb + 128);
        }
#pragma unroll
        for (int mt = 0; mt < 4; mt++) {
            mma16(acc[mt][0], ah[mt], bh[0], bh[2]);
            mma16(acc[mt][0], ah[mt], bl[0], bl[2]);
            mma16(acc[mt][0], al[mt], bh[0], bh[2]);
            mma16(acc[mt][1], ah[mt], bh[1], bh[3]);
            mma16(acc[mt][1], ah[mt], bl[1], bl[3]);
            mma16(acc[mt][1], al[mt], bh[1], bh[3]);
        }
    }
    __syncthreads();

    float* Ds = (float*)smraw;                        // [128][68]
    const int g = lane >> 2, t2 = (lane & 3) * 2;
#pragma unroll
    for (int mt = 0; mt < 4; mt++)
#pragma unroll
        for (int nt = 0; nt < 2; nt++) {
            int row = mr + mt*16 + g;
            int col = nc + nt*8 + t2;
            Ds[row*68 + col]         = fmaxf(acc[mt][nt][0], 0.f);
            Ds[row*68 + col + 1]     = fmaxf(acc[mt][nt][1], 0.f);
            Ds[(row+8)*68 + col]     = fmaxf(acc[mt][nt][2], 0.f);
            Ds[(row+8)*68 + col + 1] = fmaxf(acc[mt][nt][3], 0.f);
        }
    __syncthreads();
    float* ob = out + (size_t)row0 * 64;
#pragma unroll
    for (int it = 0; it < 8; it++) {
        int idx = tid + it * 256;
        int m = idx >> 4, o4 = (idx & 15) * 4;
        *(float4*)&ob[m*64 + o4] = *(const float4*)&Ds[m*68 + o4];
    }
}

// ---------------------------------------------------------------------------
extern "C" void kernel_launch(void* const* d_in, const int* in_sizes, int n_in,
                              void* d_out, int out_size) {
    const float* SP = nullptr; const float* W4 = nullptr;
    const float* W5 = nullptr; const float* W6 = nullptr;
    for (int i = 0; i < n_in; i++) {
        int sz = in_sizes[i];
        if (sz == 67108864)      SP = (const float*)d_in[i];
        else if (sz == 8192)     W6 = (const float*)d_in[i];
        else if (sz == 4096)     { if (!W4) W4 = (const float*)d_in[i]; else W5 = (const float*)d_in[i]; }
    }
    float* out = (float*)d_out;

    const int smem1 = 2 * (128 * AK2) * 2;                      // 69632
    const int smem2 = (128 * AK2) * 2 + 2 * (128 * K2BS) * 2;   // 71680
    const int smem3 = (128 * AK2) * 2 + (64 * BK3) * 2;         // 70656
    cudaFuncSetAttribute(k1, cudaFuncAttributeMaxDynamicSharedMemorySize, smem1);
    cudaFuncSetAttribute(k2, cudaFuncAttributeMaxDynamicSharedMemorySize, smem2);
    cudaFuncSetAttribute(k3, cudaFuncAttributeMaxDynamicSharedMemorySize, smem3);

    wprep<<<1, 256>>>(W4, W5, W6);
    k1<<<8192, 256, smem1>>>(SP);
    k2<<<8192, 256, smem2>>>();
    k3<<<8192, 256, smem3>>>(SP, out);
}

// round 16
// speedup vs baseline: 1.0165x; 1.0165x over previous
#include <cuda_runtime.h>
#include <cuda_bf16.h>
#include <cstdint>
#include <cstddef>

// 256 graphs x 64 nodes; E=1048576 rows (r = b*4096 + i*64 + j); C=64.
// K1: X=SP@W4^T/64, Y=SP@W5^T/64 -> hi/lo bf16 PLANES [b*64+c][4096]
//     (column-split: even bids -> X half, odd bids -> Y half; k3-shaped tile -> 3 CTAs/SM)
// K2: per (b, channel-pair): prod_c = X_c @ Y_c (REVERSE bid order)
// K3: out = relu(SP@W6a^T + prod@W6b^T)
// mma.sync m16n8k16 bf16; 3-term split via register reuse of hi/lo planes.
// Staging via cp.async. All GEMM kernels at 3 CTAs/SM.

__device__ unsigned short g_Xh[67108864];
__device__ unsigned short g_Xl[67108864];
__device__ unsigned short g_Yh[67108864];
__device__ unsigned short g_Yl[67108864];
__device__ unsigned short g_ph[67108864];
__device__ unsigned short g_pl[67108864];
__device__ unsigned short g_Wk1[128 * 136];   // [n][64 hi | 64 lo | pad]; rows 0-63=W4, 64-127=W5
__device__ unsigned short g_Wk3[64 * 280];

#define AK2  136
#define K2BS 72
#define BK3  280

__device__ __forceinline__ uint32_t smem_u32(const void* p) {
    uint32_t a; asm("{ .reg .u64 t; cvta.to.shared.u64 t, %1; cvt.u32.u64 %0, t; }" : "=r"(a) : "l"(p));
    return a;
}
__device__ __forceinline__ void cpa16(uint32_t sdst, const void* gsrc) {
    asm volatile("cp.async.cg.shared.global [%0], [%1], 16;" :: "r"(sdst), "l"(gsrc) : "memory");
}
#define CPA_WAIT() do { asm volatile("cp.async.commit_group;" ::: "memory"); \
                        asm volatile("cp.async.wait_group 0;" ::: "memory"); } while (0)
__device__ __forceinline__ void splitb(float v, unsigned short& h, unsigned short& l) {
    __nv_bfloat16 hb = __float2bfloat16_rn(v);
    float r = v - __bfloat162float(hb);
    __nv_bfloat16 lb = __float2bfloat16_rn(r);
    h = reinterpret_cast<unsigned short&>(hb);
    l = reinterpret_cast<unsigned short&>(lb);
}
__device__ __forceinline__ uint32_t splitpack(float v) {
    unsigned short h, l; splitb(v, h, l);
    return (uint32_t)h | ((uint32_t)l << 16);
}
__device__ __forceinline__ uint32_t prmt(uint32_t a, uint32_t b, uint32_t s) {
    uint32_t d; asm("prmt.b32 %0,%1,%2,%3;" : "=r"(d) : "r"(a), "r"(b), "r"(s)); return d;
}
__device__ __forceinline__ void ldsm4(uint32_t* r, uint32_t a) {
    asm volatile("ldmatrix.sync.aligned.m8n8.x4.shared.b16 {%0,%1,%2,%3}, [%4];"
                 : "=r"(r[0]), "=r"(r[1]), "=r"(r[2]), "=r"(r[3]) : "r"(a));
}
__device__ __forceinline__ void ldsm4t(uint32_t* r, uint32_t a) {
    asm volatile("ldmatrix.sync.aligned.m8n8.x4.trans.shared.b16 {%0,%1,%2,%3}, [%4];"
                 : "=r"(r[0]), "=r"(r[1]), "=r"(r[2]), "=r"(r[3]) : "r"(a));
}
__device__ __forceinline__ void mma16(float* c, const uint32_t* a, uint32_t b0, uint32_t b1) {
    asm volatile("mma.sync.aligned.m16n8k16.row.col.f32.bf16.bf16.f32 "
                 "{%0,%1,%2,%3},{%4,%5,%6,%7},{%8,%9},{%0,%1,%2,%3};"
                 : "+f"(c[0]), "+f"(c[1]), "+f"(c[2]), "+f"(c[3])
                 : "r"(a[0]), "r"(a[1]), "r"(a[2]), "r"(a[3]), "r"(b0), "r"(b1));
}

// ===================== weight prep =====================
__global__ void wprep(const float* __restrict__ W4, const float* __restrict__ W5,
                      const float* __restrict__ W6) {
    const int tid = threadIdx.x;
#pragma unroll
    for (int it = 0; it < 8; it++) {
        int idx = tid + it * 256;
        int n = idx >> 4, k0 = (idx & 15) * 4;
        float4 v = (n < 64) ? ((const float4*)W4)[idx] : ((const float4*)W5)[idx - 1024];
        unsigned short h0,l0,h1,l1,h2,l2,h3,l3;
        splitb(v.x,h0,l0); splitb(v.y,h1,l1); splitb(v.z,h2,l2); splitb(v.w,h3,l3);
        *(uint2*)&g_Wk1[n*AK2 + k0]      = make_uint2((uint32_t)h0|((uint32_t)h1<<16), (uint32_t)h2|((uint32_t)h3<<16));
        *(uint2*)&g_Wk1[n*AK2 + 64 + k0] = make_uint2((uint32_t)l0|((uint32_t)l1<<16), (uint32_t)l2|((uint32_t)l3<<16));
    }
#pragma unroll
    for (int it = 0; it < 8; it++) {
        int idx = tid + it * 256;
        int o = idx >> 5, m0 = (idx & 31) * 4;
        float4 v = ((const float4*)W6)[idx];
        unsigned short h0,l0,h1,l1,h2,l2,h3,l3;
        splitb(v.x,h0,l0); splitb(v.y,h1,l1); splitb(v.z,h2,l2); splitb(v.w,h3,l3);
        int s = (m0 < 64) ? 0 : 136;
        int k0 = m0 & 63;
        *(uint2*)&g_Wk3[o*BK3 + s + k0]      = make_uint2((uint32_t)h0|((uint32_t)h1<<16), (uint32_t)h2|((uint32_t)h3<<16));
        *(uint2*)&g_Wk3[o*BK3 + s + 64 + k0] = make_uint2((uint32_t)l0|((uint32_t)l1<<16), (uint32_t)l2|((uint32_t)l3<<16));
    }
}

// ===================== K1: column-split (X or Y half per CTA), 3 CTAs/SM =====================
__global__ __launch_bounds__(256, 3) void k1(const float* __restrict__ SP) {
    extern __shared__ char smraw[];
    unsigned short* As = (unsigned short*)smraw;               // [128][AK2] SP tile
    unsigned short* Bs = (unsigned short*)(smraw + 34816);     // [64][AK2] weight half
    const int tid = threadIdx.x;
    const int q = blockIdx.x >> 1, sel = blockIdx.x & 1;       // sel: 0=X(W4), 1=Y(W5)
    const int row0 = q * 128;
    const int b = row0 >> 12, rig = row0 & 4095;
    const uint32_t as_u = smem_u32(As), bs_u = smem_u32(Bs);

    // B = selected 64-row half of the pre-split weight image (1088 x 16B)
    const char* wsrc = (const char*)g_Wk1 + sel * 17408;
    for (int idx = tid; idx < 1088; idx += 256)
        cpa16(bs_u + idx * 16, wsrc + idx * 16);

    const float4* SPg = (const float4*)(SP + (size_t)row0 * 64);
#pragma unroll
    for (int it = 0; it < 8; it++) {
        int idx = tid + it * 256;
        float4 v = SPg[idx];
        int r = idx >> 4, k0 = (idx & 15) * 4;
        unsigned short h0,l0,h1,l1,h2,l2,h3,l3;
        splitb(v.x,h0,l0); splitb(v.y,h1,l1); splitb(v.z,h2,l2); splitb(v.w,h3,l3);
        *(uint2*)&As[r*AK2 + k0]      = make_uint2((uint32_t)h0|((uint32_t)h1<<16), (uint32_t)h2|((uint32_t)h3<<16));
        *(uint2*)&As[r*AK2 + 64 + k0] = make_uint2((uint32_t)l0|((uint32_t)l1<<16), (uint32_t)l2|((uint32_t)l3<<16));
    }
    CPA_WAIT();
    __syncthreads();

    const int warp = tid >> 5, lane = tid & 31;
    const int lrow = lane & 15, lcol8 = (lane >> 4) * 8;
    const int mr = (warp >> 2) * 64, nc = (warp & 3) * 16;
    float acc[4][2][4] = {};

#pragma unroll
    for (int kt = 0; kt < 4; kt++) {
        const int kk = kt * 16;
        uint32_t ah[4][4], al[4][4], bh[4], bl[4];
#pragma unroll
        for (int mt = 0; mt < 4; mt++) {
            uint32_t basea = as_u + (uint32_t)(((mr + mt*16 + lrow) * AK2) + kk + lcol8) * 2;
            ldsm4(ah[mt], basea);
            ldsm4(al[mt], basea + 128);
        }
        {
            uint32_t baseb = bs_u + (uint32_t)(((nc + lrow) * AK2) + kk + lcol8) * 2;
            ldsm4(bh, baseb);
            ldsm4(bl, baseb + 128);
        }
        // [n][k] x4: {b0@nc, b0@nc+8, b1@nc, b1@nc+8}
#pragma unroll
        for (int mt = 0; mt < 4; mt++) {
            mma16(acc[mt][0], ah[mt], bh[0], bh[2]);
            mma16(acc[mt][0], ah[mt], bl[0], bl[2]);
            mma16(acc[mt][0], al[mt], bh[0], bh[2]);
            mma16(acc[mt][1], ah[mt], bh[1], bh[3]);
            mma16(acc[mt][1], ah[mt], bl[1], bl[3]);
            mma16(acc[mt][1], al[mt], bh[1], bh[3]);
        }
    }
    __syncthreads();

    // Epilogue: Ds [64c][132m] u32 (33792 B) overlays the dead As region.
    uint32_t* Ds = (uint32_t*)smraw;
    const int g = lane >> 2, t2 = (lane & 3) * 2;
#pragma unroll
    for (int mt = 0; mt < 4; mt++)
#pragma unroll
        for (int nt = 0; nt < 2; nt++) {
            int row = mr + mt*16 + g;
            int col = nc + nt*8 + t2;
            Ds[col*132 + row]         = splitpack(acc[mt][nt][0] * 0.015625f);
            Ds[(col+1)*132 + row]     = splitpack(acc[mt][nt][1] * 0.015625f);
            Ds[col*132 + row + 8]     = splitpack(acc[mt][nt][2] * 0.015625f);
            Ds[(col+1)*132 + row + 8] = splitpack(acc[mt][nt][3] * 0.015625f);
        }
    __syncthreads();
    unsigned short* Ph = sel ? g_Yh : g_Xh;
    unsigned short* Pl = sel ? g_Yl : g_Xl;
#pragma unroll
    for (int it = 0; it < 8; it++) {
        int idx = tid + it * 256;                     // 2048 uint4 = 64c x 32
        int c = idx >> 5, m4 = (idx & 31) * 4;
        uint4 v = *(const uint4*)&Ds[c*132 + m4];
        uint2 hi = make_uint2(prmt(v.x, v.y, 0x5410), prmt(v.z, v.w, 0x5410));
        uint2 lo = make_uint2(prmt(v.x, v.y, 0x7632), prmt(v.z, v.w, 0x7632));
        size_t off = (size_t)(b*64 + c)*4096 + rig + m4;
        *(uint2*)&Ph[off] = hi; *(uint2*)&Pl[off] = lo;
    }
}

// ===================== K2 (reverse bid order for L2 reuse) =====================
__global__ __launch_bounds__(256, 3) void k2() {
    extern __shared__ char smraw[];
    unsigned short* As = (unsigned short*)smraw;      // [128][AK2]  [X_c1; X_c2]
    unsigned short* Bs = As + 128 * AK2;              // 2 x [128][K2BS]
    const int tid = threadIdx.x;
    const int bidr = 8191 - blockIdx.x;
    const int b = bidr >> 5, c1 = (bidr & 31) * 2;
    const size_t base = (size_t)(b*64 + c1) * 4096;
    const uint32_t as_u = smem_u32(As);
    const uint32_t bs_u0 = smem_u32(Bs);

#pragma unroll
    for (int it = 0; it < 8; it++) {
        int idx = tid + it * 256;
        int m = idx >> 4, pl = (idx >> 3) & 1, c8 = (idx & 7) * 8;
        const unsigned short* src = (pl ? g_Xl : g_Xh) + base + (size_t)m * 64 + c8;
        cpa16(as_u + (uint32_t)(m*AK2 + pl*64 + c8) * 2, src);
    }
#pragma unroll
    for (int it = 0; it < 8; it++) {
        int idx = tid + it * 256;
        int cid = idx >> 10, r = (idx >> 3) & 127, j8 = (idx & 7) * 8;
        const unsigned short* src = ((r < 64) ? g_Yh : g_Yl) + base + (size_t)cid * 4096
                                    + (size_t)(r & 63) * 64 + j8;
        cpa16(bs_u0 + (uint32_t)(cid*128*K2BS + r*K2BS + j8) * 2, src);
    }
    CPA_WAIT();
    __syncthreads();

    const int warp = tid >> 5, lane = tid & 31;
    const int lrow = lane & 15, lcol8 = (lane >> 4) * 8;
    const int hf = warp >> 2;
    const int mr = hf * 64, n0 = (warp & 3) * 16;
    const uint32_t bs_u = bs_u0 + (uint32_t)(hf * 128 * K2BS) * 2;
    const int brow = (lane & 7) + 8 * ((lane >> 3) & 1);
    const int bcol = n0 + 8 * (lane >> 4);
    float acc[4][2][4] = {};

#pragma unroll
    for (int kt = 0; kt < 4; kt++) {
        const int kk = kt * 16;
        uint32_t ah[4][4], al[4][4], bh[4], bl[4];
#pragma unroll
        for (int mt = 0; mt < 4; mt++) {
            uint32_t basea = as_u + (uint32_t)(((mr + mt*16 + lrow) * AK2) + kk + lcol8) * 2;
            ldsm4(ah[mt], basea);
            ldsm4(al[mt], basea + 128);
        }
        ldsm4t(bh, bs_u + (uint32_t)(((kk + brow) * K2BS) + bcol) * 2);
        ldsm4t(bl, bs_u + (uint32_t)(((64 + kk + brow) * K2BS) + bcol) * 2);
#pragma unroll
        for (int mt = 0; mt < 4; mt++) {
            mma16(acc[mt][0], ah[mt], bh[0], bh[1]);
            mma16(acc[mt][0], ah[mt], bl[0], bl[1]);
            mma16(acc[mt][0], al[mt], bh[0], bh[1]);
            mma16(acc[mt][1], ah[mt], bh[2], bh[3]);
            mma16(acc[mt][1], ah[mt], bl[2], bl[3]);
            mma16(acc[mt][1], al[mt], bh[2], bh[3]);
        }
    }
    __syncthreads();

    uint32_t* Ds = (uint32_t*)smraw;                  // [128][68] packed
    const int g = lane >> 2, t2 = (lane & 3) * 2;
#pragma unroll
    for (int mt = 0; mt < 4; mt++)
#pragma unroll
        for (int nt = 0; nt < 2; nt++) {
            int row = mr + mt*16 + g;
            int jl = (warp & 3) * 16 + nt*8 + t2;
            Ds[row*68 + jl]         = splitpack(acc[mt][nt][0]);
            Ds[row*68 + jl + 1]     = splitpack(acc[mt][nt][1]);
            Ds[(row+8)*68 + jl]     = splitpack(acc[mt][nt][2]);
            Ds[(row+8)*68 + jl + 1] = splitpack(acc[mt][nt][3]);
        }
    __syncthreads();
#pragma unroll
    for (int it = 0; it < 8; it++) {
        int idx = tid + it * 256;
        int row = idx >> 4, j4 = (idx & 15) * 4;
        uint4 v = *(const uint4*)&Ds[row*68 + j4];
        uint2 hi = make_uint2(prmt(v.x, v.y, 0x5410), prmt(v.z, v.w, 0x5410));
        uint2 lo = make_uint2(prmt(v.x, v.y, 0x7632), prmt(v.z, v.w, 0x7632));
        size_t off = base + (size_t)row * 64 + j4;
        *(uint2*)&g_ph[off] = hi; *(uint2*)&g_pl[off] = lo;
    }
}

// ===================== K3 =====================
__global__ __launch_bounds__(256, 3) void k3(const float* __restrict__ SP,
                                             float* __restrict__ out) {
    extern __shared__ char smraw[];
    unsigned short* As = (unsigned short*)smraw;               // [128][AK2]
    unsigned short* Bs = (unsigned short*)(smraw + 128*AK2*2); // [64][BK3]
    const int tid = threadIdx.x;
    const int row0 = blockIdx.x * 128;
    const int b = row0 >> 12, rig = row0 & 4095;
    const uint32_t as_u = smem_u32(As);
    const uint32_t bs_u = smem_u32(Bs);

    for (int idx = tid; idx < 2240; idx += 256)
        cpa16(bs_u + idx * 16, (const char*)g_Wk3 + idx * 16);

    const float4* SPg = (const float4*)(SP + (size_t)row0 * 64);
#pragma unroll
    for (int it = 0; it < 8; it++) {
        int idx = tid + it * 256;
        float4 v = SPg[idx];
        int r = idx >> 4, k0 = (idx & 15) * 4;
        unsigned short h0,l0,h1,l1,h2,l2,h3,l3;
        splitb(v.x,h0,l0); splitb(v.y,h1,l1); splitb(v.z,h2,l2); splitb(v.w,h3,l3);
        *(uint2*)&As[r*AK2 + k0]      = make_uint2((uint32_t)h0|((uint32_t)h1<<16), (uint32_t)h2|((uint32_t)h3<<16));
        *(uint2*)&As[r*AK2 + 64 + k0] = make_uint2((uint32_t)l0|((uint32_t)l1<<16), (uint32_t)l2|((uint32_t)l3<<16));
    }
    CPA_WAIT();
    __syncthreads();

    const int warp = tid >> 5, lane = tid & 31;
    const int lrow = lane & 15, lcol8 = (lane >> 4) * 8;
    const int mr = (warp >> 2) * 64, nc = (warp & 3) * 16;
    float acc[4][2][4] = {};

#pragma unroll
    for (int kt = 0; kt < 4; kt++) {                  // pass 1: SP @ W6a^T
        const int kk = kt * 16;
        uint32_t ah[4][4], al[4][4], bh[4], bl[4];
#pragma unroll
        for (int mt = 0; mt < 4; mt++) {
            uint32_t basea = as_u + (uint32_t)(((mr + mt*16 + lrow) * AK2) + kk + lcol8) * 2;
            ldsm4(ah[mt], basea);
            ldsm4(al[mt], basea + 128);
        }
        {
            uint32_t baseb = bs_u + (uint32_t)(((nc + lrow) * BK3) + kk + lcol8) * 2;
            ldsm4(bh, baseb);
            ldsm4(bl, baseb + 128);
        }
#pragma unroll
        for (int mt = 0; mt < 4; mt++) {
            mma16(acc[mt][0], ah[mt], bh[0], bh[2]);
            mma16(acc[mt][0], ah[mt], bl[0], bl[2]);
            mma16(acc[mt][0], al[mt], bh[0], bh[2]);
            mma16(acc[mt][1], ah[mt], bh[1], bh[3]);
            mma16(acc[mt][1], ah[mt], bl[1], bl[3]);
            mma16(acc[mt][1], al[mt], bh[1], bh[3]);
        }
    }
    __syncthreads();

    // restage A = prod in [k=c][m] layout via cp.async
#pragma unroll
    for (int it = 0; it < 8; it++) {
        int idx = tid + it * 256;
        int r = idx >> 4, m8 = (idx & 15) * 8;
        int c = r & 63;
        const unsigned short* src = ((r < 64) ? g_ph : g_pl)
                                    + (size_t)(b*64 + c) * 4096 + rig + m8;
        cpa16(as_u + (uint32_t)(r*AK2 + m8) * 2, src);
    }
    CPA_WAIT();
    __syncthreads();

    const int arow = (lane & 7) + 8 * (lane >> 4);
    const int acol8 = 8 * ((lane >> 3) & 1);
#pragma unroll
    for (int kt = 0; kt < 4; kt++) {                  // pass 2: + prod @ W6b^T
        const int kk = kt * 16;
        uint32_t ah[4][4], al[4][4], bh[4], bl[4];
#pragma unroll
        for (int mt = 0; mt < 4; mt++) {
            ldsm4t(ah[mt], as_u + (uint32_t)(((kk + arow) * AK2) + mr + mt*16 + acol8) * 2);
            ldsm4t(al[mt], as_u + (uint32_t)(((64 + kk + arow) * AK2) + mr + mt*16 + acol8) * 2);
        }
        {
            uint32_t baseb = bs_u + (uint32_t)(((nc + lrow) * BK3) + 136 + kk + lcol8) * 2;
            ldsm4(bh, baseb);
            ldsm4(bl, baseb + 128);
        }
#pragma unroll
        for (int mt = 0; mt < 4; mt++) {
            mma16(acc[mt][0], ah[mt], bh[0], bh[2]);
            mma16(acc[mt][0], ah[mt], bl[0], bl[2]);
            mma16(acc[mt][0], al[mt], bh[0], bh[2]);
            mma16(acc[mt][1], ah[mt], bh[1], bh[3]);
            mma16(acc[mt][1], ah[mt], bl[1], bl[3]);
            mma16(acc[mt][1], al[mt], bh[1], bh[3]);
        }
    }
    __syncthreads();

    float* Ds = (float*)smraw;                        // [128][68]
    const int g = lane >> 2, t2 = (lane & 3) * 2;
#pragma unroll
    for (int mt = 0; mt < 4; mt++)
#pragma unroll
        for (int nt = 0; nt < 2; nt++) {
            int row = mr + mt*16 + g;
            int col = nc + nt*8 + t2;
            Ds[row*68 + col]         = fmaxf(acc[mt][nt][0], 0.f);
            Ds[row*68 + col + 1]     = fmaxf(acc[mt][nt][1], 0.f);
            Ds[(row+8)*68 + col]     = fmaxf(acc[mt][nt][2], 0.f);
            Ds[(row+8)*68 + col + 1] = fmaxf(acc[mt][nt][3], 0.f);
        }
    __syncthreads();
    float* ob = out + (size_t)row0 * 64;
#pragma unroll
    for (int it = 0; it < 8; it++) {
        int idx = tid + it * 256;
        int m = idx >> 4, o4 = (idx & 15) * 4;
        *(float4*)&ob[m*64 + o4] = *(const float4*)&Ds[m*68 + o4];
    }
}

// ---------------------------------------------------------------------------
extern "C" void kernel_launch(void* const* d_in, const int* in_sizes, int n_in,
                              void* d_out, int out_size) {
    const float* SP = nullptr; const float* W4 = nullptr;
    const float* W5 = nullptr; const float* W6 = nullptr;
    for (int i = 0; i < n_in; i++) {
        int sz = in_sizes[i];
        if (sz == 67108864)      SP = (const float*)d_in[i];
        else if (sz == 8192)     W6 = (const float*)d_in[i];
        else if (sz == 4096)     { if (!W4) W4 = (const float*)d_in[i]; else W5 = (const float*)d_in[i]; }
    }
    float* out = (float*)d_out;

    const int smem1 = 34816 + 64 * AK2 * 2;                     // 52224
    const int smem2 = (128 * AK2) * 2 + 2 * (128 * K2BS) * 2;   // 71680
    const int smem3 = (128 * AK2) * 2 + (64 * BK3) * 2;         // 70656
    cudaFuncSetAttribute(k1, cudaFuncAttributeMaxDynamicSharedMemorySize, smem1);
    cudaFuncSetAttribute(k2, cudaFuncAttributeMaxDynamicSharedMemorySize, smem2);
    cudaFuncSetAttribute(k3, cudaFuncAttributeMaxDynamicSharedMemorySize, smem3);

    wprep<<<1, 256>>>(W4, W5, W6);
    k1<<<16384, 256, smem1>>>(SP);
    k2<<<8192, 256, smem2>>>();
    k3<<<8192, 256, smem3>>>(SP, out);
}

// round 17
// speedup vs baseline: 1.0332x; 1.0165x over previous
#include <cuda_runtime.h>
#include <cuda_bf16.h>
#include <cstdint>
#include <cstddef>

// 256 graphs x 64 nodes; E=1048576 rows (r = b*4096 + i*64 + j); C=64.
// K1: X=SP@W4^T/64, Y=SP@W5^T/64 -> hi/lo bf16 PLANES (column-split per CTA), 4 CTAs/SM
// K2: per (b, channel-pair): prod_c = X_c @ Y_c (REVERSE bid order), 3 CTAs/SM
// K3: out = relu(SP@W6a^T + prod@W6b^T), W6 halves staged per pass, 4 CTAs/SM
// mma.sync m16n8k16 bf16; 3-term split via register reuse of hi/lo planes.

__device__ unsigned short g_Xh[67108864];
__device__ unsigned short g_Xl[67108864];
__device__ unsigned short g_Yh[67108864];
__device__ unsigned short g_Yl[67108864];
__device__ unsigned short g_ph[67108864];
__device__ unsigned short g_pl[67108864];
__device__ unsigned short g_Wk1[128 * 136];   // [n][64 hi | 64 lo | pad]; rows 0-63=W4, 64-127=W5
__device__ unsigned short g_Wk3[2 * 64 * 136];// half h at h*8704: [o][64 hi | 64 lo | pad]

#define AK2  136
#define K2BS 72

__device__ __forceinline__ uint32_t smem_u32(const void* p) {
    uint32_t a; asm("{ .reg .u64 t; cvta.to.shared.u64 t, %1; cvt.u32.u64 %0, t; }" : "=r"(a) : "l"(p));
    return a;
}
__device__ __forceinline__ void cpa16(uint32_t sdst, const void* gsrc) {
    asm volatile("cp.async.cg.shared.global [%0], [%1], 16;" :: "r"(sdst), "l"(gsrc) : "memory");
}
#define CPA_WAIT() do { asm volatile("cp.async.commit_group;" ::: "memory"); \
                        asm volatile("cp.async.wait_group 0;" ::: "memory"); } while (0)
__device__ __forceinline__ void splitb(float v, unsigned short& h, unsigned short& l) {
    __nv_bfloat16 hb = __float2bfloat16_rn(v);
    float r = v - __bfloat162float(hb);
    __nv_bfloat16 lb = __float2bfloat16_rn(r);
    h = reinterpret_cast<unsigned short&>(hb);
    l = reinterpret_cast<unsigned short&>(lb);
}
__device__ __forceinline__ uint32_t splitpack(float v) {
    unsigned short h, l; splitb(v, h, l);
    return (uint32_t)h | ((uint32_t)l << 16);
}
__device__ __forceinline__ uint32_t prmt(uint32_t a, uint32_t b, uint32_t s) {
    uint32_t d; asm("prmt.b32 %0,%1,%2,%3;" : "=r"(d) : "r"(a), "r"(b), "r"(s)); return d;
}
__device__ __forceinline__ void ldsm4(uint32_t* r, uint32_t a) {
    asm volatile("ldmatrix.sync.aligned.m8n8.x4.shared.b16 {%0,%1,%2,%3}, [%4];"
                 : "=r"(r[0]), "=r"(r[1]), "=r"(r[2]), "=r"(r[3]) : "r"(a));
}
__device__ __forceinline__ void ldsm4t(uint32_t* r, uint32_t a) {
    asm volatile("ldmatrix.sync.aligned.m8n8.x4.trans.shared.b16 {%0,%1,%2,%3}, [%4];"
                 : "=r"(r[0]), "=r"(r[1]), "=r"(r[2]), "=r"(r[3]) : "r"(a));
}
__device__ __forceinline__ void mma16(float* c, const uint32_t* a, uint32_t b0, uint32_t b1) {
    asm volatile("mma.sync.aligned.m16n8k16.row.col.f32.bf16.bf16.f32 "
                 "{%0,%1,%2,%3},{%4,%5,%6,%7},{%8,%9},{%0,%1,%2,%3};"
                 : "+f"(c[0]), "+f"(c[1]), "+f"(c[2]), "+f"(c[3])
                 : "r"(a[0]), "r"(a[1]), "r"(a[2]), "r"(a[3]), "r"(b0), "r"(b1));
}

// ===================== weight prep =====================
__global__ void wprep(const float* __restrict__ W4, const float* __restrict__ W5,
                      const float* __restrict__ W6) {
    const int tid = threadIdx.x;
#pragma unroll
    for (int it = 0; it < 8; it++) {
        int idx = tid + it * 256;
        int n = idx >> 4, k0 = (idx & 15) * 4;
        float4 v = (n < 64) ? ((const float4*)W4)[idx] : ((const float4*)W5)[idx - 1024];
        unsigned short h0,l0,h1,l1,h2,l2,h3,l3;
        splitb(v.x,h0,l0); splitb(v.y,h1,l1); splitb(v.z,h2,l2); splitb(v.w,h3,l3);
        *(uint2*)&g_Wk1[n*AK2 + k0]      = make_uint2((uint32_t)h0|((uint32_t)h1<<16), (uint32_t)h2|((uint32_t)h3<<16));
        *(uint2*)&g_Wk1[n*AK2 + 64 + k0] = make_uint2((uint32_t)l0|((uint32_t)l1<<16), (uint32_t)l2|((uint32_t)l3<<16));
    }
#pragma unroll
    for (int it = 0; it < 8; it++) {
        int idx = tid + it * 256;
        int o = idx >> 5, m0 = (idx & 31) * 4;
        float4 v = ((const float4*)W6)[idx];
        unsigned short h0,l0,h1,l1,h2,l2,h3,l3;
        splitb(v.x,h0,l0); splitb(v.y,h1,l1); splitb(v.z,h2,l2); splitb(v.w,h3,l3);
        int s = (m0 < 64) ? 0 : 8704;                // contiguous halves
        int k0 = m0 & 63;
        *(uint2*)&g_Wk3[s + o*AK2 + k0]      = make_uint2((uint32_t)h0|((uint32_t)h1<<16), (uint32_t)h2|((uint32_t)h3<<16));
        *(uint2*)&g_Wk3[s + o*AK2 + 64 + k0] = make_uint2((uint32_t)l0|((uint32_t)l1<<16), (uint32_t)l2|((uint32_t)l3<<16));
    }
}

// ===================== K1: column-split (X or Y half per CTA), 4 CTAs/SM =====================
__global__ __launch_bounds__(256, 4) void k1(const float* __restrict__ SP) {
    extern __shared__ char smraw[];
    unsigned short* As = (unsigned short*)smraw;               // [128][AK2] SP tile
    unsigned short* Bs = (unsigned short*)(smraw + 34816);     // [64][AK2] weight half
    const int tid = threadIdx.x;
    const int q = blockIdx.x >> 1, sel = blockIdx.x & 1;       // sel: 0=X(W4), 1=Y(W5)
    const int row0 = q * 128;
    const int b = row0 >> 12, rig = row0 & 4095;
    const uint32_t as_u = smem_u32(As), bs_u = smem_u32(Bs);

    const char* wsrc = (const char*)g_Wk1 + sel * 17408;
    for (int idx = tid; idx < 1088; idx += 256)
        cpa16(bs_u + idx * 16, wsrc + idx * 16);

    const float4* SPg = (const float4*)(SP + (size_t)row0 * 64);
#pragma unroll
    for (int it = 0; it < 8; it++) {
        int idx = tid + it * 256;
        float4 v = SPg[idx];
        int r = idx >> 4, k0 = (idx & 15) * 4;
        unsigned short h0,l0,h1,l1,h2,l2,h3,l3;
        splitb(v.x,h0,l0); splitb(v.y,h1,l1); splitb(v.z,h2,l2); splitb(v.w,h3,l3);
        *(uint2*)&As[r*AK2 + k0]      = make_uint2((uint32_t)h0|((uint32_t)h1<<16), (uint32_t)h2|((uint32_t)h3<<16));
        *(uint2*)&As[r*AK2 + 64 + k0] = make_uint2((uint32_t)l0|((uint32_t)l1<<16), (uint32_t)l2|((uint32_t)l3<<16));
    }
    CPA_WAIT();
    __syncthreads();

    const int warp = tid >> 5, lane = tid & 31;
    const int lrow = lane & 15, lcol8 = (lane >> 4) * 8;
    const int mr = (warp >> 2) * 64, nc = (warp & 3) * 16;
    float acc[4][2][4] = {};

#pragma unroll
    for (int kt = 0; kt < 4; kt++) {
        const int kk = kt * 16;
        uint32_t ah[4][4], al[4][4], bh[4], bl[4];
#pragma unroll
        for (int mt = 0; mt < 4; mt++) {
            uint32_t basea = as_u + (uint32_t)(((mr + mt*16 + lrow) * AK2) + kk + lcol8) * 2;
            ldsm4(ah[mt], basea);
            ldsm4(al[mt], basea + 128);
        }
        {
            uint32_t baseb = bs_u + (uint32_t)(((nc + lrow) * AK2) + kk + lcol8) * 2;
            ldsm4(bh, baseb);
            ldsm4(bl, baseb + 128);
        }
#pragma unroll
        for (int mt = 0; mt < 4; mt++) {
            mma16(acc[mt][0], ah[mt], bh[0], bh[2]);
            mma16(acc[mt][0], ah[mt], bl[0], bl[2]);
            mma16(acc[mt][0], al[mt], bh[0], bh[2]);
            mma16(acc[mt][1], ah[mt], bh[1], bh[3]);
            mma16(acc[mt][1], ah[mt], bl[1], bl[3]);
            mma16(acc[mt][1], al[mt], bh[1], bh[3]);
        }
    }
    __syncthreads();

    uint32_t* Ds = (uint32_t*)smraw;                  // [64c][132m] overlays As
    const int g = lane >> 2, t2 = (lane & 3) * 2;
#pragma unroll
    for (int mt = 0; mt < 4; mt++)
#pragma unroll
        for (int nt = 0; nt < 2; nt++) {
            int row = mr + mt*16 + g;
            int col = nc + nt*8 + t2;
            Ds[col*132 + row]         = splitpack(acc[mt][nt][0] * 0.015625f);
            Ds[(col+1)*132 + row]     = splitpack(acc[mt][nt][1] * 0.015625f);
            Ds[col*132 + row + 8]     = splitpack(acc[mt][nt][2] * 0.015625f);
            Ds[(col+1)*132 + row + 8] = splitpack(acc[mt][nt][3] * 0.015625f);
        }
    __syncthreads();
    unsigned short* Ph = sel ? g_Yh : g_Xh;
    unsigned short* Pl = sel ? g_Yl : g_Xl;
#pragma unroll
    for (int it = 0; it < 8; it++) {
        int idx = tid + it * 256;
        int c = idx >> 5, m4 = (idx & 31) * 4;
        uint4 v = *(const uint4*)&Ds[c*132 + m4];
        uint2 hi = make_uint2(prmt(v.x, v.y, 0x5410), prmt(v.z, v.w, 0x5410));
        uint2 lo = make_uint2(prmt(v.x, v.y, 0x7632), prmt(v.z, v.w, 0x7632));
        size_t off = (size_t)(b*64 + c)*4096 + rig + m4;
        *(uint2*)&Ph[off] = hi; *(uint2*)&Pl[off] = lo;
    }
}

// ===================== K2 (reverse bid order for L2 reuse), 3 CTAs/SM =====================
__global__ __launch_bounds__(256, 3) void k2() {
    extern __shared__ char smraw[];
    unsigned short* As = (unsigned short*)smraw;      // [128][AK2]  [X_c1; X_c2]
    unsigned short* Bs = As + 128 * AK2;              // 2 x [128][K2BS]
    const int tid = threadIdx.x;
    const int bidr = 8191 - blockIdx.x;
    const int b = bidr >> 5, c1 = (bidr & 31) * 2;
    const size_t base = (size_t)(b*64 + c1) * 4096;
    const uint32_t as_u = smem_u32(As);
    const uint32_t bs_u0 = smem_u32(Bs);

#pragma unroll
    for (int it = 0; it < 8; it++) {
        int idx = tid + it * 256;
        int m = idx >> 4, pl = (idx >> 3) & 1, c8 = (idx & 7) * 8;
        const unsigned short* src = (pl ? g_Xl : g_Xh) + base + (size_t)m * 64 + c8;
        cpa16(as_u + (uint32_t)(m*AK2 + pl*64 + c8) * 2, src);
    }
#pragma unroll
    for (int it = 0; it < 8; it++) {
        int idx = tid + it * 256;
        int cid = idx >> 10, r = (idx >> 3) & 127, j8 = (idx & 7) * 8;
        const unsigned short* src = ((r < 64) ? g_Yh : g_Yl) + base + (size_t)cid * 4096
                                    + (size_t)(r & 63) * 64 + j8;
        cpa16(bs_u0 + (uint32_t)(cid*128*K2BS + r*K2BS + j8) * 2, src);
    }
    CPA_WAIT();
    __syncthreads();

    const int warp = tid >> 5, lane = tid & 31;
    const int lrow = lane & 15, lcol8 = (lane >> 4) * 8;
    const int hf = warp >> 2;
    const int mr = hf * 64, n0 = (warp & 3) * 16;
    const uint32_t bs_u = bs_u0 + (uint32_t)(hf * 128 * K2BS) * 2;
    const int brow = (lane & 7) + 8 * ((lane >> 3) & 1);
    const int bcol = n0 + 8 * (lane >> 4);
    float acc[4][2][4] = {};

#pragma unroll
    for (int kt = 0; kt < 4; kt++) {
        const int kk = kt * 16;
        uint32_t ah[4][4], al[4][4], bh[4], bl[4];
#pragma unroll
        for (int mt = 0; mt < 4; mt++) {
            uint32_t basea = as_u + (uint32_t)(((mr + mt*16 + lrow) * AK2) + kk + lcol8) * 2;
            ldsm4(ah[mt], basea);
            ldsm4(al[mt], basea + 128);
        }
        ldsm4t(bh, bs_u + (uint32_t)(((kk + brow) * K2BS) + bcol) * 2);
        ldsm4t(bl, bs_u + (uint32_t)(((64 + kk + brow) * K2BS) + bcol) * 2);
#pragma unroll
        for (int mt = 0; mt < 4; mt++) {
            mma16(acc[mt][0], ah[mt], bh[0], bh[1]);
            mma16(acc[mt][0], ah[mt], bl[0], bl[1]);
            mma16(acc[mt][0], al[mt], bh[0], bh[1]);
            mma16(acc[mt][1], ah[mt], bh[2], bh[3]);
            mma16(acc[mt][1], ah[mt], bl[2], bl[3]);
            mma16(acc[mt][1], al[mt], bh[2], bh[3]);
        }
    }
    __syncthreads();

    uint32_t* Ds = (uint32_t*)smraw;                  // [128][68] packed
    const int g = lane >> 2, t2 = (lane & 3) * 2;
#pragma unroll
    for (int mt = 0; mt < 4; mt++)
#pragma unroll
        for (int nt = 0; nt < 2; nt++) {
            int row = mr + mt*16 + g;
            int jl = (warp & 3) * 16 + nt*8 + t2;
            Ds[row*68 + jl]         = splitpack(acc[mt][nt][0]);
            Ds[row*68 + jl + 1]     = splitpack(acc[mt][nt][1]);
            Ds[(row+8)*68 + jl]     = splitpack(acc[mt][nt][2]);
            Ds[(row+8)*68 + jl + 1] = splitpack(acc[mt][nt][3]);
        }
    __syncthreads();
#pragma unroll
    for (int it = 0; it < 8; it++) {
        int idx = tid + it * 256;
        int row = idx >> 4, j4 = (idx & 15) * 4;
        uint4 v = *(const uint4*)&Ds[row*68 + j4];
        uint2 hi = make_uint2(prmt(v.x, v.y, 0x5410), prmt(v.z, v.w, 0x5410));
        uint2 lo = make_uint2(prmt(v.x, v.y, 0x7632), prmt(v.z, v.w, 0x7632));
        size_t off = base + (size_t)row * 64 + j4;
        *(uint2*)&g_ph[off] = hi; *(uint2*)&g_pl[off] = lo;
    }
}

// ===================== K3: W6 halves staged per pass, 4 CTAs/SM =====================
__global__ __launch_bounds__(256, 4) void k3(const float* __restrict__ SP,
                                             float* __restrict__ out) {
    extern __shared__ char smraw[];
    unsigned short* As = (unsigned short*)smraw;               // [128][AK2]
    unsigned short* Bs = (unsigned short*)(smraw + 34816);     // [64][AK2] W6 half
    const int tid = threadIdx.x;
    const int row0 = blockIdx.x * 128;
    const int b = row0 >> 12, rig = row0 & 4095;
    const uint32_t as_u = smem_u32(As);
    const uint32_t bs_u = smem_u32(Bs);

    // pass-1 weights (W6a half)
    for (int idx = tid; idx < 1088; idx += 256)
        cpa16(bs_u + idx * 16, (const char*)g_Wk3 + idx * 16);

    const float4* SPg = (const float4*)(SP + (size_t)row0 * 64);
#pragma unroll
    for (int it = 0; it < 8; it++) {
        int idx = tid + it * 256;
        float4 v = SPg[idx];
        int r = idx >> 4, k0 = (idx & 15) * 4;
        unsigned short h0,l0,h1,l1,h2,l2,h3,l3;
        splitb(v.x,h0,l0); splitb(v.y,h1,l1); splitb(v.z,h2,l2); splitb(v.w,h3,l3);
        *(uint2*)&As[r*AK2 + k0]      = make_uint2((uint32_t)h0|((uint32_t)h1<<16), (uint32_t)h2|((uint32_t)h3<<16));
        *(uint2*)&As[r*AK2 + 64 + k0] = make_uint2((uint32_t)l0|((uint32_t)l1<<16), (uint32_t)l2|((uint32_t)l3<<16));
    }
    CPA_WAIT();
    __syncthreads();

    const int warp = tid >> 5, lane = tid & 31;
    const int lrow = lane & 15, lcol8 = (lane >> 4) * 8;
    const int mr = (warp >> 2) * 64, nc = (warp & 3) * 16;
    float acc[4][2][4] = {};

#pragma unroll
    for (int kt = 0; kt < 4; kt++) {                  // pass 1: SP @ W6a^T
        const int kk = kt * 16;
        uint32_t ah[4][4], al[4][4], bh[4], bl[4];
#pragma unroll
        for (int mt = 0; mt < 4; mt++) {
            uint32_t basea = as_u + (uint32_t)(((mr + mt*16 + lrow) * AK2) + kk + lcol8) * 2;
            ldsm4(ah[mt], basea);
            ldsm4(al[mt], basea + 128);
        }
        {
            uint32_t baseb = bs_u + (uint32_t)(((nc + lrow) * AK2) + kk + lcol8) * 2;
            ldsm4(bh, baseb);
            ldsm4(bl, baseb + 128);
        }
#pragma unroll
        for (int mt = 0; mt < 4; mt++) {
            mma16(acc[mt][0], ah[mt], bh[0], bh[2]);
            mma16(acc[mt][0], ah[mt], bl[0], bl[2]);
            mma16(acc[mt][0], al[mt], bh[0], bh[2]);
            mma16(acc[mt][1], ah[mt], bh[1], bh[3]);
            mma16(acc[mt][1], ah[mt], bl[1], bl[3]);
            mma16(acc[mt][1], al[mt], bh[1], bh[3]);
        }
    }
    __syncthreads();

    // restage: A = prod [k=c][m], B = W6b half
#pragma unroll
    for (int it = 0; it < 8; it++) {
        int idx = tid + it * 256;
        int r = idx >> 4, m8 = (idx & 15) * 8;
        int c = r & 63;
        const unsigned short* src = ((r < 64) ? g_ph : g_pl)
                                    + (size_t)(b*64 + c) * 4096 + rig + m8;
        cpa16(as_u + (uint32_t)(r*AK2 + m8) * 2, src);
    }
    for (int idx = tid; idx < 1088; idx += 256)
        cpa16(bs_u + idx * 16, (const char*)(g_Wk3 + 8704) + idx * 16);
    CPA_WAIT();
    __syncthreads();

    const int arow = (lane & 7) + 8 * (lane >> 4);
    const int acol8 = 8 * ((lane >> 3) & 1);
#pragma unroll
    for (int kt = 0; kt < 4; kt++) {                  // pass 2: + prod @ W6b^T
        const int kk = kt * 16;
        uint32_t ah[4][4], al[4][4], bh[4], bl[4];
#pragma unroll
        for (int mt = 0; mt < 4; mt++) {
            ldsm4t(ah[mt], as_u + (uint32_t)(((kk + arow) * AK2) + mr + mt*16 + acol8) * 2);
            ldsm4t(al[mt], as_u + (uint32_t)(((64 + kk + arow) * AK2) + mr + mt*16 + acol8) * 2);
        }
        {
            uint32_t baseb = bs_u + (uint32_t)(((nc + lrow) * AK2) + kk + lcol8) * 2;
            ldsm4(bh, baseb);
            ldsm4(bl, baseb + 128);
        }
#pragma unroll
        for (int mt = 0; mt < 4; mt++) {
            mma16(acc[mt][0], ah[mt], bh[0], bh[2]);
            mma16(acc[mt][0], ah[mt], bl[0], bl[2]);
            mma16(acc[mt][0], al[mt], bh[0], bh[2]);
            mma16(acc[mt][1], ah[mt], bh[1], bh[3]);
            mma16(acc[mt][1], ah[mt], bl[1], bl[3]);
            mma16(acc[mt][1], al[mt], bh[1], bh[3]);
        }
    }
    __syncthreads();

    float* Ds = (float*)smraw;                        // [128][68] overlays As (34816+ Bs region unused for first 64 rows... fits: 128*68*4=34816 exactly)
    const int g = lane >> 2, t2 = (lane & 3) * 2;
#pragma unroll
    for (int mt = 0; mt < 4; mt++)
#pragma unroll
        for (int nt = 0; nt < 2; nt++) {
            int row = mr + mt*16 + g;
            int col = nc + nt*8 + t2;
            Ds[row*68 + col]         = fmaxf(acc[mt][nt][0], 0.f);
            Ds[row*68 + col + 1]     = fmaxf(acc[mt][nt][1], 0.f);
            Ds[(row+8)*68 + col]     = fmaxf(acc[mt][nt][2], 0.f);
            Ds[(row+8)*68 + col + 1] = fmaxf(acc[mt][nt][3], 0.f);
        }
    __syncthreads();
    float* ob = out + (size_t)row0 * 64;
#pragma unroll
    for (int it = 0; it < 8; it++) {
        int idx = tid + it * 256;
        int m = idx >> 4, o4 = (idx & 15) * 4;
        *(float4*)&ob[m*64 + o4] = *(const float4*)&Ds[m*68 + o4];
    }
}

// ---------------------------------------------------------------------------
extern "C" void kernel_launch(void* const* d_in, const int* in_sizes, int n_in,
                              void* d_out, int out_size) {
    const float* SP = nullptr; const float* W4 = nullptr;
    const float* W5 = nullptr; const float* W6 = nullptr;
    for (int i = 0; i < n_in; i++) {
        int sz = in_sizes[i];
        if (sz == 67108864)      SP = (const float*)d_in[i];
        else if (sz == 8192)     W6 = (const float*)d_in[i];
        else if (sz == 4096)     { if (!W4) W4 = (const float*)d_in[i]; else W5 = (const float*)d_in[i]; }
    }
    float* out = (float*)d_out;

    const int smem1 = 34816 + 17408;                            // 52224
    const int smem2 = (128 * AK2) * 2 + 2 * (128 * K2BS) * 2;   // 71680
    const int smem3 = 34816 + 17408;                            // 52224
    cudaFuncSetAttribute(k1, cudaFuncAttributeMaxDynamicSharedMemorySize, smem1);
    cudaFuncSetAttribute(k2, cudaFuncAttributeMaxDynamicSharedMemorySize, smem2);
    cudaFuncSetAttribute(k3, cudaFuncAttributeMaxDynamicSharedMemorySize, smem3);

    wprep<<<1, 256>>>(W4, W5, W6);
    k1<<<16384, 256, smem1>>>(SP);
    k2<<<8192, 256, smem2>>>();
    k3<<<8192, 256, smem3>>>(SP, out);
}